// round 15
// baseline (speedup 1.0000x reference)
#include <cuda_runtime.h>
#include <cuda_fp16.h>
#include <cstdint>

#define MAXN 50000
#define MAXE 800000
#define HID  128
#define OUTC 64

typedef unsigned long long ull;

// ---------------------------------------------------------------------------
// Scratch (__device__ globals; no allocation allowed)
// g_csr has 32 slack entries (zero-init, never written) so unclamped index
// prefetch may safely overread past off[N].
// ---------------------------------------------------------------------------
__device__ __half g_y1h[MAXN * HID];
__device__ __half g_y2h[MAXN * OUTC];
__device__ int    g_cnt [MAXN];          // zeroed at load; re-zeroed by lsm
__device__ int    g_off [MAXN + 1];
__device__ int    g_rank[MAXE];
__device__ int    g_csr [MAXE + 32];
__device__ int    g_done;                // last-block ticket (self-resetting)

// ---------------------------------------------------------------------------
// Streams/events for fork-join inside graph capture
// ---------------------------------------------------------------------------
static cudaStream_t g_s1;
static cudaEvent_t  g_evA, g_evB;
static struct StreamInit {
    StreamInit() {
        cudaStreamCreateWithFlags(&g_s1, cudaStreamNonBlocking);
        cudaEventCreateWithFlags(&g_evA, cudaEventDisableTiming);
        cudaEventCreateWithFlags(&g_evB, cudaEventDisableTiming);
    }
} g_stream_init;

// ---------------------------------------------------------------------------
// Helpers
// ---------------------------------------------------------------------------
__device__ __forceinline__ uint32_t smem_u32(const void* p) {
    return (uint32_t)__cvta_generic_to_shared(p);
}
__device__ __forceinline__ __half2 as_h2(uint32_t v) {
    return *reinterpret_cast<__half2*>(&v);
}
__device__ __forceinline__ float4 cvt_h4(uint2 u) {
    float2 fa = __half22float2(as_h2(u.x));
    float2 fb = __half22float2(as_h2(u.y));
    return make_float4(fa.x, fa.y, fb.x, fb.y);
}

// ---------------------------------------------------------------------------
// count+rank+scan fused (last-block-done). 1024 threads/block, 2 edges/thr.
// ---------------------------------------------------------------------------
__global__ void __launch_bounds__(1024)
count_scan_kernel(const int* __restrict__ dst, int E2, int N) {
    int i = blockIdx.x * blockDim.x + threadIdx.x;
    if (i < E2) {
        int2 d = __ldg(reinterpret_cast<const int2*>(dst) + i);
        int2 r;
        r.x = atomicAdd(&g_cnt[d.x], 1);
        r.y = atomicAdd(&g_cnt[d.y], 1);
        reinterpret_cast<int2*>(g_rank)[i] = r;
    }
    __threadfence();
    __shared__ int isLast;
    if (threadIdx.x == 0) {
        int done = atomicAdd(&g_done, 1);
        isLast = (done == (int)gridDim.x - 1);
        if (isLast) g_done = 0;
    }
    __syncthreads();
    if (!isLast) return;

    __shared__ int warp_sums[32];
    __shared__ int carry_s;
    int t = threadIdx.x;
    int lane = t & 31, wid = t >> 5;
    int N4 = N >> 2;
    const int4* cnt4 = reinterpret_cast<const int4*>(g_cnt);
    int4* off4 = reinterpret_cast<int4*>(g_off);
    if (t == 0) carry_s = 0;
    __syncthreads();
    for (int base4 = 0; base4 < N4; base4 += 1024) {
        int idx4 = base4 + t;
        int4 v = (idx4 < N4) ? cnt4[idx4] : make_int4(0, 0, 0, 0);
        int s = v.x + v.y + v.z + v.w;
        int incl = s;
#pragma unroll
        for (int o = 1; o < 32; o <<= 1) {
            int u = __shfl_up_sync(~0u, incl, o);
            if (lane >= o) incl += u;
        }
        if (lane == 31) warp_sums[wid] = incl;
        __syncthreads();
        if (t < 32) {
            int w = warp_sums[t];
#pragma unroll
            for (int o = 1; o < 32; o <<= 1) {
                int u = __shfl_up_sync(~0u, w, o);
                if (t >= o) w += u;
            }
            warp_sums[t] = w;
        }
        __syncthreads();
        int woff = (wid > 0) ? warp_sums[wid - 1] : 0;
        int excl = incl - s + woff + carry_s;
        if (idx4 < N4) {
            int4 o;
            o.x = excl;
            o.y = excl + v.x;
            o.z = excl + v.x + v.y;
            o.w = excl + v.x + v.y + v.z;
            off4[idx4] = o;
        }
        __syncthreads();
        if (t == 0) carry_s += warp_sums[31];
        __syncthreads();
    }
    if (t == 0) g_off[N] = carry_s;
}

__global__ void scatter_kernel(const int* __restrict__ src,
                               const int* __restrict__ dst, int E2) {
    int i = blockIdx.x * blockDim.x + threadIdx.x;
    if (i >= E2) return;
    int2 s = __ldg(reinterpret_cast<const int2*>(src) + i);
    int2 d = __ldg(reinterpret_cast<const int2*>(dst) + i);
    int2 r = reinterpret_cast<const int2*>(g_rank)[i];
    g_csr[__ldg(&g_off[d.x]) + r.x] = s.x;
    g_csr[__ldg(&g_off[d.y]) + r.y] = s.y;
}

// ---------------------------------------------------------------------------
// GEMM1 (tensor cores): y1h[N,128] = half( x[N,128] @ W1[128,128] )
// ---------------------------------------------------------------------------
#define G1_SMEM (2 * 128 * 136 * 2)

__global__ void __launch_bounds__(256, 2)
gemm1_kernel(const float* __restrict__ A, const float* __restrict__ W,
             __half* __restrict__ out, int N) {
    extern __shared__ char dynsm[];
    __half* As = reinterpret_cast<__half*>(dynsm);             // [128][136]
    __half* Ws = reinterpret_cast<__half*>(dynsm) + 128 * 136; // [128][136]

    const int t = threadIdx.x;
    const int row0 = blockIdx.x * 128;

#pragma unroll
    for (int i = 0; i < 16; i++) {
        int idx = t + i * 256;
        int m = idx >> 5;
        int c4 = idx & 31;
        int gr = row0 + m;
        float4 a = (gr < N)
            ? __ldg(reinterpret_cast<const float4*>(A + (size_t)gr * 128 + c4 * 4))
            : make_float4(0.f, 0.f, 0.f, 0.f);
        *reinterpret_cast<__half2*>(&As[m * 136 + c4 * 4])     = __floats2half2_rn(a.x, a.y);
        *reinterpret_cast<__half2*>(&As[m * 136 + c4 * 4 + 2]) = __floats2half2_rn(a.z, a.w);
    }
#pragma unroll
    for (int i = 0; i < 16; i++) {
        int idx = t + i * 256;
        int k = idx >> 5, c4 = idx & 31;
        float4 w = __ldg(reinterpret_cast<const float4*>(W + (size_t)k * 128 + c4 * 4));
        *reinterpret_cast<__half2*>(&Ws[k * 136 + c4 * 4])     = __floats2half2_rn(w.x, w.y);
        *reinterpret_cast<__half2*>(&Ws[k * 136 + c4 * 4 + 2]) = __floats2half2_rn(w.z, w.w);
    }
    __syncthreads();

    const int warp = t >> 5, lane = t & 31;
    const int m0 = warp * 16;

    float acc[16][4];
#pragma unroll
    for (int i = 0; i < 16; i++)
#pragma unroll
        for (int j = 0; j < 4; j++) acc[i][j] = 0.f;

#pragma unroll
    for (int kk = 0; kk < 8; kk++) {
        uint32_t a0, a1, a2, a3;
        uint32_t aaddr = smem_u32(
            &As[(m0 + (lane & 15)) * 136 + kk * 16 + ((lane >> 4) << 3)]);
        asm volatile("ldmatrix.sync.aligned.m8n8.x4.shared.b16 {%0,%1,%2,%3}, [%4];"
                     : "=r"(a0), "=r"(a1), "=r"(a2), "=r"(a3) : "r"(aaddr));
#pragma unroll
        for (int nt = 0; nt < 16; nt++) {
            uint32_t b0, b1;
            uint32_t baddr = smem_u32(&Ws[(kk * 16 + (lane & 15)) * 136 + nt * 8]);
            asm volatile("ldmatrix.sync.aligned.m8n8.x2.trans.shared.b16 {%0,%1}, [%2];"
                         : "=r"(b0), "=r"(b1) : "r"(baddr));
            asm volatile(
                "mma.sync.aligned.m16n8k16.row.col.f32.f16.f16.f32 "
                "{%0,%1,%2,%3}, {%4,%5,%6,%7}, {%8,%9}, {%0,%1,%2,%3};"
                : "+f"(acc[nt][0]), "+f"(acc[nt][1]),
                  "+f"(acc[nt][2]), "+f"(acc[nt][3])
                : "r"(a0), "r"(a1), "r"(a2), "r"(a3), "r"(b0), "r"(b1));
        }
    }

    const int g = lane >> 2, tg = lane & 3;
    const int r0 = row0 + m0 + g;
    const int r1 = r0 + 8;
#pragma unroll
    for (int nt = 0; nt < 16; nt++) {
        int col = nt * 8 + 2 * tg;
        if (r0 < N)
            *reinterpret_cast<__half2*>(&out[(size_t)r0 * 128 + col]) =
                __floats2half2_rn(acc[nt][0], acc[nt][1]);
        if (r1 < N)
            *reinterpret_cast<__half2*>(&out[(size_t)r1 * 128 + col]) =
                __floats2half2_rn(acc[nt][2], acc[nt][3]);
    }
}

// fp16 tree-reduce 6 uint4 into fp32 accumulators
__device__ __forceinline__ void tree6(const uint4* u, float4& a0, float4& a1) {
    __half2 tx = __hadd2(__hadd2(__hadd2(as_h2(u[0].x), as_h2(u[1].x)),
                                 __hadd2(as_h2(u[2].x), as_h2(u[3].x))),
                         __hadd2(as_h2(u[4].x), as_h2(u[5].x)));
    __half2 ty = __hadd2(__hadd2(__hadd2(as_h2(u[0].y), as_h2(u[1].y)),
                                 __hadd2(as_h2(u[2].y), as_h2(u[3].y))),
                         __hadd2(as_h2(u[4].y), as_h2(u[5].y)));
    __half2 tz = __hadd2(__hadd2(__hadd2(as_h2(u[0].z), as_h2(u[1].z)),
                                 __hadd2(as_h2(u[2].z), as_h2(u[3].z))),
                         __hadd2(as_h2(u[4].z), as_h2(u[5].z)));
    __half2 tw = __hadd2(__hadd2(__hadd2(as_h2(u[0].w), as_h2(u[1].w)),
                                 __hadd2(as_h2(u[2].w), as_h2(u[3].w))),
                         __hadd2(as_h2(u[4].w), as_h2(u[5].w)));
    float2 fx = __half22float2(tx), fy = __half22float2(ty);
    float2 fz = __half22float2(tz), fw = __half22float2(tw);
    a0.x += fx.x; a0.y += fx.y; a0.z += fy.x; a0.w += fy.y;
    a1.x += fz.x; a1.y += fz.y; a1.z += fw.x; a1.w += fw.y;
}

// fp16 tree-reduce 8 uint4 into fp32 accumulators
__device__ __forceinline__ void tree8w(const uint4* u, float4& a0, float4& a1) {
    __half2 tx = __hadd2(__hadd2(__hadd2(as_h2(u[0].x), as_h2(u[1].x)),
                                 __hadd2(as_h2(u[2].x), as_h2(u[3].x))),
                         __hadd2(__hadd2(as_h2(u[4].x), as_h2(u[5].x)),
                                 __hadd2(as_h2(u[6].x), as_h2(u[7].x))));
    __half2 ty = __hadd2(__hadd2(__hadd2(as_h2(u[0].y), as_h2(u[1].y)),
                                 __hadd2(as_h2(u[2].y), as_h2(u[3].y))),
                         __hadd2(__hadd2(as_h2(u[4].y), as_h2(u[5].y)),
                                 __hadd2(as_h2(u[6].y), as_h2(u[7].y))));
    __half2 tz = __hadd2(__hadd2(__hadd2(as_h2(u[0].z), as_h2(u[1].z)),
                                 __hadd2(as_h2(u[2].z), as_h2(u[3].z))),
                         __hadd2(__hadd2(as_h2(u[4].z), as_h2(u[5].z)),
                                 __hadd2(as_h2(u[6].z), as_h2(u[7].z))));
    __half2 tw = __hadd2(__hadd2(__hadd2(as_h2(u[0].w), as_h2(u[1].w)),
                                 __hadd2(as_h2(u[2].w), as_h2(u[3].w))),
                         __hadd2(__hadd2(as_h2(u[4].w), as_h2(u[5].w)),
                                 __hadd2(as_h2(u[6].w), as_h2(u[7].w))));
    float2 fx = __half22float2(tx), fy = __half22float2(ty);
    float2 fz = __half22float2(tz), fw = __half22float2(tw);
    a0.x += fx.x; a0.y += fx.y; a0.z += fy.x; a0.w += fy.y;
    a1.x += fz.x; a1.y += fz.y; a1.z += fw.x; a1.w += fw.y;
}

// ---------------------------------------------------------------------------
// FUSED: wide-gather pull-agg (16 lanes x uint4/row, 12 edges/burst) with
// unclamped pipelined index prefetch, fp16 tree reduction -> fp16 smem tile
// -> HMMA GEMM2. 512 threads, 16 warps, 4 nodes/warp.
// ---------------------------------------------------------------------------
#define AS_STRIDE 136
#define WS_STRIDE 72
#define FUSE_SMEM ((64 * AS_STRIDE + 128 * WS_STRIDE) * 2)

__global__ void __launch_bounds__(512, 2)
agg_gemm_kernel(const __half* __restrict__ Y1h, const float* __restrict__ W2,
                const float* __restrict__ b1, const float* __restrict__ b2,
                const float* __restrict__ cv1, __half* __restrict__ y2, int N) {
    extern __shared__ char dynsm[];
    __half* As = reinterpret_cast<__half*>(dynsm);                   // [64][136]
    __half* Ws = reinterpret_cast<__half*>(dynsm) + 64 * AS_STRIDE;  // [128][72]

    const int t = threadIdx.x;
    const int row0 = blockIdx.x * 64;
    const int warp = t >> 5, lane = t & 31;

    // Load W2 fp32 -> fp16 smem
#pragma unroll
    for (int i = 0; i < 4; i++) {
        int idx = t + i * 512;
        int k = idx >> 4;
        int c4 = idx & 15;
        float4 w = __ldg(reinterpret_cast<const float4*>(W2) + idx);
        *reinterpret_cast<__half2*>(&Ws[k * WS_STRIDE + c4 * 4])     = __floats2half2_rn(w.x, w.y);
        *reinterpret_cast<__half2*>(&Ws[k * WS_STRIDE + c4 * 4 + 2]) = __floats2half2_rn(w.z, w.w);
    }

    // ---- Wide aggregation: warp -> 4 nodes; half-warp -> one edge each ----
    {
        const uint4* Y4 = reinterpret_cast<const uint4*>(Y1h);  // row = 16 uint4
        const int eo = lane >> 4;
        const int li = lane & 15;
        float sc = -fabsf(__ldg(cv1));
#pragma unroll
        for (int ni = 0; ni < 4; ni++) {
            int m = warp * 4 + ni;
            int r = row0 + m;
            if (r < N) {
                float4 a0 = make_float4(0.f, 0.f, 0.f, 0.f);
                float4 a1 = make_float4(0.f, 0.f, 0.f, 0.f);
                if (eo == 0) {
                    uint4 su = __ldg(Y4 + (size_t)r * 16 + li);
                    a0 = cvt_h4(make_uint2(su.x, su.y));
                    a1 = cvt_h4(make_uint2(su.z, su.w));
                }
                int st = g_off[r], en = g_off[r + 1];
                int i = st;
                int s[6];
#pragma unroll
                for (int j = 0; j < 6; j++)
                    s[j] = __ldg(g_csr + i + 2 * j + eo);
                for (; i + 12 <= en; ) {
                    uint4 u[6];
#pragma unroll
                    for (int j = 0; j < 6; j++)
                        u[j] = __ldg(Y4 + (size_t)s[j] * 16 + li);
                    i += 12;
#pragma unroll
                    for (int j = 0; j < 6; j++)
                        s[j] = __ldg(g_csr + i + 2 * j + eo);
                    tree6(u, a0, a1);
                }
                if (i < en) {
                    uint4 u[6];
#pragma unroll
                    for (int j = 0; j < 6; j++) {
                        u[j] = __ldg(Y4 + (size_t)s[j] * 16 + li);
                        if (i + 2 * j + eo >= en) u[j] = make_uint4(0, 0, 0, 0);
                    }
                    tree6(u, a0, a1);
                }
                a0.x += __shfl_xor_sync(~0u, a0.x, 16);
                a0.y += __shfl_xor_sync(~0u, a0.y, 16);
                a0.z += __shfl_xor_sync(~0u, a0.z, 16);
                a0.w += __shfl_xor_sync(~0u, a0.w, 16);
                a1.x += __shfl_xor_sync(~0u, a1.x, 16);
                a1.y += __shfl_xor_sync(~0u, a1.y, 16);
                a1.z += __shfl_xor_sync(~0u, a1.z, 16);
                a1.w += __shfl_xor_sync(~0u, a1.w, 16);
                if (eo == 0) {
                    float deg = (float)(en - st + 1);
                    float4 bb0 = __ldg(reinterpret_cast<const float4*>(b1) + 2 * li);
                    float4 bb1 = __ldg(reinterpret_cast<const float4*>(b1) + 2 * li + 1);
                    float4 o0, o1;
                    o0.x = fmaxf(0.f, sc * (a0.x + deg * bb0.x));
                    o0.y = fmaxf(0.f, sc * (a0.y + deg * bb0.y));
                    o0.z = fmaxf(0.f, sc * (a0.z + deg * bb0.z));
                    o0.w = fmaxf(0.f, sc * (a0.w + deg * bb0.w));
                    o1.x = fmaxf(0.f, sc * (a1.x + deg * bb1.x));
                    o1.y = fmaxf(0.f, sc * (a1.y + deg * bb1.y));
                    o1.z = fmaxf(0.f, sc * (a1.z + deg * bb1.z));
                    o1.w = fmaxf(0.f, sc * (a1.w + deg * bb1.w));
                    uint4 pk;
                    __half2 h0 = __floats2half2_rn(o0.x, o0.y);
                    __half2 h1 = __floats2half2_rn(o0.z, o0.w);
                    __half2 h2 = __floats2half2_rn(o1.x, o1.y);
                    __half2 h3 = __floats2half2_rn(o1.z, o1.w);
                    pk.x = *reinterpret_cast<unsigned*>(&h0);
                    pk.y = *reinterpret_cast<unsigned*>(&h1);
                    pk.z = *reinterpret_cast<unsigned*>(&h2);
                    pk.w = *reinterpret_cast<unsigned*>(&h3);
                    *reinterpret_cast<uint4*>(&As[m * AS_STRIDE + li * 8]) = pk;
                }
            } else if (eo == 0) {
                *reinterpret_cast<uint4*>(&As[m * AS_STRIDE + li * 8]) =
                    make_uint4(0, 0, 0, 0);
            }
        }
    }
    __syncthreads();

    // ---- HMMA GEMM phase: 64x64 tile; 16 warps, 1 m-tile x 2 n-tiles each --
    {
        const int mt = warp >> 2;
        const int nt0 = (warp & 3) * 2;
        const int m0 = mt * 16;

        float acc[2][4];
#pragma unroll
        for (int i = 0; i < 2; i++)
#pragma unroll
            for (int j = 0; j < 4; j++) acc[i][j] = 0.f;

#pragma unroll
        for (int kk = 0; kk < 8; kk++) {
            uint32_t a0, a1, a2, a3;
            uint32_t aaddr = smem_u32(
                &As[(m0 + (lane & 15)) * AS_STRIDE + kk * 16 + ((lane >> 4) << 3)]);
            asm volatile("ldmatrix.sync.aligned.m8n8.x4.shared.b16 {%0,%1,%2,%3}, [%4];"
                         : "=r"(a0), "=r"(a1), "=r"(a2), "=r"(a3) : "r"(aaddr));
#pragma unroll
            for (int j = 0; j < 2; j++) {
                uint32_t b0, b1;
                uint32_t baddr = smem_u32(
                    &Ws[(kk * 16 + (lane & 15)) * WS_STRIDE + (nt0 + j) * 8]);
                asm volatile("ldmatrix.sync.aligned.m8n8.x2.trans.shared.b16 {%0,%1}, [%2];"
                             : "=r"(b0), "=r"(b1) : "r"(baddr));
                asm volatile(
                    "mma.sync.aligned.m16n8k16.row.col.f32.f16.f16.f32 "
                    "{%0,%1,%2,%3}, {%4,%5,%6,%7}, {%8,%9}, {%0,%1,%2,%3};"
                    : "+f"(acc[j][0]), "+f"(acc[j][1]),
                      "+f"(acc[j][2]), "+f"(acc[j][3])
                    : "r"(a0), "r"(a1), "r"(a2), "r"(a3), "r"(b0), "r"(b1));
            }
        }

        const int g = lane >> 2, tg = lane & 3;
        const int r0 = row0 + m0 + g;
        const int r1 = r0 + 8;
#pragma unroll
        for (int j = 0; j < 2; j++) {
            int col = (nt0 + j) * 8 + 2 * tg;
            float bb0 = __ldg(b2 + col), bb1 = __ldg(b2 + col + 1);
            if (r0 < N)
                *reinterpret_cast<__half2*>(&y2[(size_t)r0 * OUTC + col]) =
                    __floats2half2_rn(acc[j][0] + bb0, acc[j][1] + bb1);
            if (r1 < N)
                *reinterpret_cast<__half2*>(&y2[(size_t)r1 * OUTC + col]) =
                    __floats2half2_rn(acc[j][2] + bb0, acc[j][3] + bb1);
        }
    }
}

// ---------------------------------------------------------------------------
// Ultra-wide pull-agg layer 2 + log_softmax: 8 lanes x uint4 per 128B row,
// 4 edges/load, 32 edges/burst, unclamped pipelined prefetch, fp16 tree.
// Quarter-warp partial sums merged via shfl_xor(8,16). Re-zeros g_cnt.
// ---------------------------------------------------------------------------
__global__ void __launch_bounds__(256)
pull_agg64_lsm_kernel(const __half* __restrict__ Yh,
                      const float* __restrict__ curv,
                      float* __restrict__ out, int N) {
    int gid = blockIdx.x * blockDim.x + threadIdx.x;
    if (gid < N) g_cnt[gid] = 0;   // prepare count buffer for next replay

    int warp = gid >> 5;
    int lane = threadIdx.x & 31;
    if (warp >= N) return;
    const uint4* Yv = reinterpret_cast<const uint4*>(Yh);  // row = 8 uint4
    const int eo = lane >> 3;        // edge slot 0..3
    const int li = lane & 7;         // 16B chunk within row (8 cols)

    float4 a0 = make_float4(0.f, 0.f, 0.f, 0.f);
    float4 a1 = make_float4(0.f, 0.f, 0.f, 0.f);
    if (eo == 0) {                   // self loop counted once
        uint4 su = __ldg(Yv + (size_t)warp * 8 + li);
        a0 = cvt_h4(make_uint2(su.x, su.y));
        a1 = cvt_h4(make_uint2(su.z, su.w));
    }
    int st = g_off[warp], en = g_off[warp + 1];
    int i = st;
    int s[8];
#pragma unroll
    for (int j = 0; j < 8; j++)
        s[j] = __ldg(g_csr + i + 4 * j + eo);       // unclamped (slack OK)
    for (; i + 32 <= en; ) {
        uint4 u[8];
#pragma unroll
        for (int j = 0; j < 8; j++)
            u[j] = __ldg(Yv + (size_t)s[j] * 8 + li);
        i += 32;
#pragma unroll
        for (int j = 0; j < 8; j++)
            s[j] = __ldg(g_csr + i + 4 * j + eo);   // unclamped prefetch
        tree8w(u, a0, a1);
    }
    if (i < en) {
        uint4 u[8];
#pragma unroll
        for (int j = 0; j < 8; j++) {
            u[j] = __ldg(Yv + (size_t)s[j] * 8 + li);
            if (i + 4 * j + eo >= en) u[j] = make_uint4(0, 0, 0, 0);
        }
        tree8w(u, a0, a1);
    }
    // merge the 4 quarter-warp partial sums
#pragma unroll
    for (int o = 8; o <= 16; o <<= 1) {
        a0.x += __shfl_xor_sync(~0u, a0.x, o);
        a0.y += __shfl_xor_sync(~0u, a0.y, o);
        a0.z += __shfl_xor_sync(~0u, a0.z, o);
        a0.w += __shfl_xor_sync(~0u, a0.w, o);
        a1.x += __shfl_xor_sync(~0u, a1.x, o);
        a1.y += __shfl_xor_sync(~0u, a1.y, o);
        a1.z += __shfl_xor_sync(~0u, a1.z, o);
        a1.w += __shfl_xor_sync(~0u, a1.w, o);
    }

    float sc = -fabsf(__ldg(curv));
    float v0 = sc * a0.x, v1 = sc * a0.y, v2 = sc * a0.z, v3 = sc * a0.w;
    float v4 = sc * a1.x, v5 = sc * a1.y, v6 = sc * a1.z, v7 = sc * a1.w;
    float m = fmaxf(fmaxf(fmaxf(v0, v1), fmaxf(v2, v3)),
                    fmaxf(fmaxf(v4, v5), fmaxf(v6, v7)));
#pragma unroll
    for (int o = 4; o; o >>= 1) m = fmaxf(m, __shfl_xor_sync(~0u, m, o));
    float sum = expf(v0 - m) + expf(v1 - m) + expf(v2 - m) + expf(v3 - m)
              + expf(v4 - m) + expf(v5 - m) + expf(v6 - m) + expf(v7 - m);
#pragma unroll
    for (int o = 4; o; o >>= 1) sum += __shfl_xor_sync(~0u, sum, o);
    float lse = m + logf(sum);
    if (eo == 0) {
        float4 q0 = make_float4(v0 - lse, v1 - lse, v2 - lse, v3 - lse);
        float4 q1 = make_float4(v4 - lse, v5 - lse, v6 - lse, v7 - lse);
        *reinterpret_cast<float4*>(&out[(size_t)warp * OUTC + li * 8])     = q0;
        *reinterpret_cast<float4*>(&out[(size_t)warp * OUTC + li * 8 + 4]) = q1;
    }
}

// ---------------------------------------------------------------------------
// Launch. Submission order: count_scan #1, scatter #2, gemm1 #3,
// agg_gemm #4 (ncu capture slot), lsm #5.
// ---------------------------------------------------------------------------
extern "C" void kernel_launch(void* const* d_in, const int* in_sizes, int n_in,
                              void* d_out, int out_size) {
    const float* x   = (const float*)d_in[0];
    const int*   ei  = (const int*)d_in[1];
    const float* W1  = (const float*)d_in[2];
    const float* b1  = (const float*)d_in[3];
    const float* cv1 = (const float*)d_in[6];
    const float* W2  = (const float*)d_in[7];
    const float* b2  = (const float*)d_in[8];
    const float* cv2 = (const float*)d_in[11];
    float* out = (float*)d_out;

    int N = in_sizes[0] / HID;
    int E = in_sizes[1] / 2;
    if (N > MAXN) N = MAXN;
    if (E > MAXE) E = MAXE;
    const int* src = ei;
    const int* dst = ei + E;
    int E2 = E / 2;

    void *y1p, *y2p;
    cudaGetSymbolAddress(&y1p, g_y1h);
    cudaGetSymbolAddress(&y2p, g_y2h);

    cudaFuncSetAttribute(agg_gemm_kernel,
                         cudaFuncAttributeMaxDynamicSharedMemorySize, FUSE_SMEM);
    cudaFuncSetAttribute(gemm1_kernel,
                         cudaFuncAttributeMaxDynamicSharedMemorySize, G1_SMEM);

    // Fork: CSR build on side stream (overlaps gemm1)
    cudaEventRecord(g_evA, 0);
    cudaStreamWaitEvent(g_s1, g_evA, 0);
    count_scan_kernel<<<(E2 + 1023) / 1024, 1024, 0, g_s1>>>(dst, E2, N); // #1
    scatter_kernel<<<(E2 + 255) / 256, 256, 0, g_s1>>>(src, dst, E2);     // #2
    cudaEventRecord(g_evB, g_s1);

    // Main stream: y1 = half(x @ W1) on tensor cores
    gemm1_kernel<<<(N + 127) / 128, 256, G1_SMEM>>>(x, W1, (__half*)y1p, N); // #3

    // Join, then fused agg1+epi+HMMA gemm2  (ncu capture slot #4)
    cudaStreamWaitEvent(0, g_evB, 0);
    agg_gemm_kernel<<<(N + 63) / 64, 512, FUSE_SMEM>>>(
        (const __half*)y1p, W2, b1, b2, cv1, (__half*)y2p, N);            // #4

    // agg2 + log_softmax fused (+ g_cnt re-zero for next replay)
    pull_agg64_lsm_kernel<<<(N * 32 + 255) / 256, 256>>>(
        (const __half*)y2p, cv2, out, N);                                 // #5
}

// round 16
// speedup vs baseline: 1.0595x; 1.0595x over previous
#include <cuda_runtime.h>
#include <cuda_fp16.h>
#include <cstdint>

#define MAXN 50000
#define MAXE 800000
#define HID  128
#define OUTC 64

typedef unsigned long long ull;

// ---------------------------------------------------------------------------
// Scratch (__device__ globals; no allocation allowed)
// g_csr has 32 slack entries (zero-init, never written) so unclamped index
// prefetch may safely overread past off[N].
// ---------------------------------------------------------------------------
__device__ __half g_y1h[MAXN * HID];
__device__ __half g_y2h[MAXN * OUTC];
__device__ int    g_cnt [MAXN];          // zeroed at load; re-zeroed by lsm
__device__ int    g_off [MAXN + 1];
__device__ int    g_rank[MAXE];
__device__ int    g_csr [MAXE + 32];
__device__ int    g_done;                // last-block ticket (self-resetting)

// ---------------------------------------------------------------------------
// Streams/events for fork-join inside graph capture
// ---------------------------------------------------------------------------
static cudaStream_t g_s1;
static cudaEvent_t  g_evA, g_evB;
static struct StreamInit {
    StreamInit() {
        cudaStreamCreateWithFlags(&g_s1, cudaStreamNonBlocking);
        cudaEventCreateWithFlags(&g_evA, cudaEventDisableTiming);
        cudaEventCreateWithFlags(&g_evB, cudaEventDisableTiming);
    }
} g_stream_init;

// ---------------------------------------------------------------------------
// Helpers
// ---------------------------------------------------------------------------
__device__ __forceinline__ uint32_t smem_u32(const void* p) {
    return (uint32_t)__cvta_generic_to_shared(p);
}
__device__ __forceinline__ __half2 as_h2(uint32_t v) {
    return *reinterpret_cast<__half2*>(&v);
}
__device__ __forceinline__ float4 cvt_h4(uint2 u) {
    float2 fa = __half22float2(as_h2(u.x));
    float2 fb = __half22float2(as_h2(u.y));
    return make_float4(fa.x, fa.y, fb.x, fb.y);
}

// ---------------------------------------------------------------------------
// count+rank+scan fused (last-block-done). 1024 threads/block, 2 edges/thr.
// ---------------------------------------------------------------------------
__global__ void __launch_bounds__(1024)
count_scan_kernel(const int* __restrict__ dst, int E2, int N) {
    int i = blockIdx.x * blockDim.x + threadIdx.x;
    if (i < E2) {
        int2 d = __ldg(reinterpret_cast<const int2*>(dst) + i);
        int2 r;
        r.x = atomicAdd(&g_cnt[d.x], 1);
        r.y = atomicAdd(&g_cnt[d.y], 1);
        reinterpret_cast<int2*>(g_rank)[i] = r;
    }
    __threadfence();
    __shared__ int isLast;
    if (threadIdx.x == 0) {
        int done = atomicAdd(&g_done, 1);
        isLast = (done == (int)gridDim.x - 1);
        if (isLast) g_done = 0;
    }
    __syncthreads();
    if (!isLast) return;

    __shared__ int warp_sums[32];
    __shared__ int carry_s;
    int t = threadIdx.x;
    int lane = t & 31, wid = t >> 5;
    int N4 = N >> 2;
    const int4* cnt4 = reinterpret_cast<const int4*>(g_cnt);
    int4* off4 = reinterpret_cast<int4*>(g_off);
    if (t == 0) carry_s = 0;
    __syncthreads();
    for (int base4 = 0; base4 < N4; base4 += 1024) {
        int idx4 = base4 + t;
        int4 v = (idx4 < N4) ? cnt4[idx4] : make_int4(0, 0, 0, 0);
        int s = v.x + v.y + v.z + v.w;
        int incl = s;
#pragma unroll
        for (int o = 1; o < 32; o <<= 1) {
            int u = __shfl_up_sync(~0u, incl, o);
            if (lane >= o) incl += u;
        }
        if (lane == 31) warp_sums[wid] = incl;
        __syncthreads();
        if (t < 32) {
            int w = warp_sums[t];
#pragma unroll
            for (int o = 1; o < 32; o <<= 1) {
                int u = __shfl_up_sync(~0u, w, o);
                if (t >= o) w += u;
            }
            warp_sums[t] = w;
        }
        __syncthreads();
        int woff = (wid > 0) ? warp_sums[wid - 1] : 0;
        int excl = incl - s + woff + carry_s;
        if (idx4 < N4) {
            int4 o;
            o.x = excl;
            o.y = excl + v.x;
            o.z = excl + v.x + v.y;
            o.w = excl + v.x + v.y + v.z;
            off4[idx4] = o;
        }
        __syncthreads();
        if (t == 0) carry_s += warp_sums[31];
        __syncthreads();
    }
    if (t == 0) g_off[N] = carry_s;
}

__global__ void scatter_kernel(const int* __restrict__ src,
                               const int* __restrict__ dst, int E2) {
    int i = blockIdx.x * blockDim.x + threadIdx.x;
    if (i >= E2) return;
    int2 s = __ldg(reinterpret_cast<const int2*>(src) + i);
    int2 d = __ldg(reinterpret_cast<const int2*>(dst) + i);
    int2 r = reinterpret_cast<const int2*>(g_rank)[i];
    g_csr[__ldg(&g_off[d.x]) + r.x] = s.x;
    g_csr[__ldg(&g_off[d.y]) + r.y] = s.y;
}

// ---------------------------------------------------------------------------
// GEMM1 (tensor cores): y1h[N,128] = half( x[N,128] @ W1[128,128] )
// ---------------------------------------------------------------------------
#define G1_SMEM (2 * 128 * 136 * 2)

__global__ void __launch_bounds__(256, 2)
gemm1_kernel(const float* __restrict__ A, const float* __restrict__ W,
             __half* __restrict__ out, int N) {
    extern __shared__ char dynsm[];
    __half* As = reinterpret_cast<__half*>(dynsm);             // [128][136]
    __half* Ws = reinterpret_cast<__half*>(dynsm) + 128 * 136; // [128][136]

    const int t = threadIdx.x;
    const int row0 = blockIdx.x * 128;

#pragma unroll
    for (int i = 0; i < 16; i++) {
        int idx = t + i * 256;
        int m = idx >> 5;
        int c4 = idx & 31;
        int gr = row0 + m;
        float4 a = (gr < N)
            ? __ldg(reinterpret_cast<const float4*>(A + (size_t)gr * 128 + c4 * 4))
            : make_float4(0.f, 0.f, 0.f, 0.f);
        *reinterpret_cast<__half2*>(&As[m * 136 + c4 * 4])     = __floats2half2_rn(a.x, a.y);
        *reinterpret_cast<__half2*>(&As[m * 136 + c4 * 4 + 2]) = __floats2half2_rn(a.z, a.w);
    }
#pragma unroll
    for (int i = 0; i < 16; i++) {
        int idx = t + i * 256;
        int k = idx >> 5, c4 = idx & 31;
        float4 w = __ldg(reinterpret_cast<const float4*>(W + (size_t)k * 128 + c4 * 4));
        *reinterpret_cast<__half2*>(&Ws[k * 136 + c4 * 4])     = __floats2half2_rn(w.x, w.y);
        *reinterpret_cast<__half2*>(&Ws[k * 136 + c4 * 4 + 2]) = __floats2half2_rn(w.z, w.w);
    }
    __syncthreads();

    const int warp = t >> 5, lane = t & 31;
    const int m0 = warp * 16;

    float acc[16][4];
#pragma unroll
    for (int i = 0; i < 16; i++)
#pragma unroll
        for (int j = 0; j < 4; j++) acc[i][j] = 0.f;

#pragma unroll
    for (int kk = 0; kk < 8; kk++) {
        uint32_t a0, a1, a2, a3;
        uint32_t aaddr = smem_u32(
            &As[(m0 + (lane & 15)) * 136 + kk * 16 + ((lane >> 4) << 3)]);
        asm volatile("ldmatrix.sync.aligned.m8n8.x4.shared.b16 {%0,%1,%2,%3}, [%4];"
                     : "=r"(a0), "=r"(a1), "=r"(a2), "=r"(a3) : "r"(aaddr));
#pragma unroll
        for (int nt = 0; nt < 16; nt++) {
            uint32_t b0, b1;
            uint32_t baddr = smem_u32(&Ws[(kk * 16 + (lane & 15)) * 136 + nt * 8]);
            asm volatile("ldmatrix.sync.aligned.m8n8.x2.trans.shared.b16 {%0,%1}, [%2];"
                         : "=r"(b0), "=r"(b1) : "r"(baddr));
            asm volatile(
                "mma.sync.aligned.m16n8k16.row.col.f32.f16.f16.f32 "
                "{%0,%1,%2,%3}, {%4,%5,%6,%7}, {%8,%9}, {%0,%1,%2,%3};"
                : "+f"(acc[nt][0]), "+f"(acc[nt][1]),
                  "+f"(acc[nt][2]), "+f"(acc[nt][3])
                : "r"(a0), "r"(a1), "r"(a2), "r"(a3), "r"(b0), "r"(b1));
        }
    }

    const int g = lane >> 2, tg = lane & 3;
    const int r0 = row0 + m0 + g;
    const int r1 = r0 + 8;
#pragma unroll
    for (int nt = 0; nt < 16; nt++) {
        int col = nt * 8 + 2 * tg;
        if (r0 < N)
            *reinterpret_cast<__half2*>(&out[(size_t)r0 * 128 + col]) =
                __floats2half2_rn(acc[nt][0], acc[nt][1]);
        if (r1 < N)
            *reinterpret_cast<__half2*>(&out[(size_t)r1 * 128 + col]) =
                __floats2half2_rn(acc[nt][2], acc[nt][3]);
    }
}

// fp16 tree-reduce 6 uint4 into fp32 accumulators
__device__ __forceinline__ void tree6(const uint4* u, float4& a0, float4& a1) {
    __half2 tx = __hadd2(__hadd2(__hadd2(as_h2(u[0].x), as_h2(u[1].x)),
                                 __hadd2(as_h2(u[2].x), as_h2(u[3].x))),
                         __hadd2(as_h2(u[4].x), as_h2(u[5].x)));
    __half2 ty = __hadd2(__hadd2(__hadd2(as_h2(u[0].y), as_h2(u[1].y)),
                                 __hadd2(as_h2(u[2].y), as_h2(u[3].y))),
                         __hadd2(as_h2(u[4].y), as_h2(u[5].y)));
    __half2 tz = __hadd2(__hadd2(__hadd2(as_h2(u[0].z), as_h2(u[1].z)),
                                 __hadd2(as_h2(u[2].z), as_h2(u[3].z))),
                         __hadd2(as_h2(u[4].z), as_h2(u[5].z)));
    __half2 tw = __hadd2(__hadd2(__hadd2(as_h2(u[0].w), as_h2(u[1].w)),
                                 __hadd2(as_h2(u[2].w), as_h2(u[3].w))),
                         __hadd2(as_h2(u[4].w), as_h2(u[5].w)));
    float2 fx = __half22float2(tx), fy = __half22float2(ty);
    float2 fz = __half22float2(tz), fw = __half22float2(tw);
    a0.x += fx.x; a0.y += fx.y; a0.z += fy.x; a0.w += fy.y;
    a1.x += fz.x; a1.y += fz.y; a1.z += fw.x; a1.w += fw.y;
}

// fp16 tree-reduce 8 uint2 into fp32 accumulator
__device__ __forceinline__ void tree8(const uint2* u, float4& acc) {
    __half2 tx = __hadd2(__hadd2(__hadd2(as_h2(u[0].x), as_h2(u[1].x)),
                                 __hadd2(as_h2(u[2].x), as_h2(u[3].x))),
                         __hadd2(__hadd2(as_h2(u[4].x), as_h2(u[5].x)),
                                 __hadd2(as_h2(u[6].x), as_h2(u[7].x))));
    __half2 ty = __hadd2(__hadd2(__hadd2(as_h2(u[0].y), as_h2(u[1].y)),
                                 __hadd2(as_h2(u[2].y), as_h2(u[3].y))),
                         __hadd2(__hadd2(as_h2(u[4].y), as_h2(u[5].y)),
                                 __hadd2(as_h2(u[6].y), as_h2(u[7].y))));
    float2 fx = __half22float2(tx), fy = __half22float2(ty);
    acc.x += fx.x; acc.y += fx.y; acc.z += fy.x; acc.w += fy.y;
}

// ---------------------------------------------------------------------------
// FUSED PERSISTENT: grid-stride over 64-node tiles. W2 loaded/converted ONCE
// per block. Per tile: wide-gather pull-agg (16 lanes x uint4/row, 12
// edges/burst, unclamped pipelined index prefetch, fp16 tree) -> fp16 smem
// tile -> HMMA GEMM2. 512 threads, 16 warps, 4 nodes/warp.
// ---------------------------------------------------------------------------
#define AS_STRIDE 136
#define WS_STRIDE 72
#define FUSE_SMEM ((64 * AS_STRIDE + 128 * WS_STRIDE) * 2)

__global__ void __launch_bounds__(512, 2)
agg_gemm_kernel(const __half* __restrict__ Y1h, const float* __restrict__ W2,
                const float* __restrict__ b1, const float* __restrict__ b2,
                const float* __restrict__ cv1, __half* __restrict__ y2, int N) {
    extern __shared__ char dynsm[];
    __half* As = reinterpret_cast<__half*>(dynsm);                   // [64][136]
    __half* Ws = reinterpret_cast<__half*>(dynsm) + 64 * AS_STRIDE;  // [128][72]

    const int t = threadIdx.x;
    const int warp = t >> 5, lane = t & 31;

    // Load W2 fp32 -> fp16 smem ONCE per block
#pragma unroll
    for (int i = 0; i < 4; i++) {
        int idx = t + i * 512;
        int k = idx >> 4;
        int c4 = idx & 15;
        float4 w = __ldg(reinterpret_cast<const float4*>(W2) + idx);
        *reinterpret_cast<__half2*>(&Ws[k * WS_STRIDE + c4 * 4])     = __floats2half2_rn(w.x, w.y);
        *reinterpret_cast<__half2*>(&Ws[k * WS_STRIDE + c4 * 4 + 2]) = __floats2half2_rn(w.z, w.w);
    }

    const int ntiles = (N + 63) >> 6;
    const uint4* Y4 = reinterpret_cast<const uint4*>(Y1h);  // row = 16 uint4
    const int eo = lane >> 4;
    const int li = lane & 15;
    const float sc = -fabsf(__ldg(cv1));

    for (int tile = blockIdx.x; tile < ntiles; tile += gridDim.x) {
        const int row0 = tile * 64;

        // ---- Aggregation: warp -> 4 nodes; half-warp -> one edge each ----
#pragma unroll
        for (int ni = 0; ni < 4; ni++) {
            int m = warp * 4 + ni;
            int r = row0 + m;
            if (r < N) {
                float4 a0 = make_float4(0.f, 0.f, 0.f, 0.f);
                float4 a1 = make_float4(0.f, 0.f, 0.f, 0.f);
                if (eo == 0) {
                    uint4 su = __ldg(Y4 + (size_t)r * 16 + li);
                    a0 = cvt_h4(make_uint2(su.x, su.y));
                    a1 = cvt_h4(make_uint2(su.z, su.w));
                }
                int st = g_off[r], en = g_off[r + 1];
                int i = st;
                int s[6];
#pragma unroll
                for (int j = 0; j < 6; j++)
                    s[j] = __ldg(g_csr + i + 2 * j + eo);
                for (; i + 12 <= en; ) {
                    uint4 u[6];
#pragma unroll
                    for (int j = 0; j < 6; j++)
                        u[j] = __ldg(Y4 + (size_t)s[j] * 16 + li);
                    i += 12;
#pragma unroll
                    for (int j = 0; j < 6; j++)
                        s[j] = __ldg(g_csr + i + 2 * j + eo);
                    tree6(u, a0, a1);
                }
                if (i < en) {
                    uint4 u[6];
#pragma unroll
                    for (int j = 0; j < 6; j++) {
                        u[j] = __ldg(Y4 + (size_t)s[j] * 16 + li);
                        if (i + 2 * j + eo >= en) u[j] = make_uint4(0, 0, 0, 0);
                    }
                    tree6(u, a0, a1);
                }
                a0.x += __shfl_xor_sync(~0u, a0.x, 16);
                a0.y += __shfl_xor_sync(~0u, a0.y, 16);
                a0.z += __shfl_xor_sync(~0u, a0.z, 16);
                a0.w += __shfl_xor_sync(~0u, a0.w, 16);
                a1.x += __shfl_xor_sync(~0u, a1.x, 16);
                a1.y += __shfl_xor_sync(~0u, a1.y, 16);
                a1.z += __shfl_xor_sync(~0u, a1.z, 16);
                a1.w += __shfl_xor_sync(~0u, a1.w, 16);
                if (eo == 0) {
                    float deg = (float)(en - st + 1);
                    float4 bb0 = __ldg(reinterpret_cast<const float4*>(b1) + 2 * li);
                    float4 bb1 = __ldg(reinterpret_cast<const float4*>(b1) + 2 * li + 1);
                    float4 o0, o1;
                    o0.x = fmaxf(0.f, sc * (a0.x + deg * bb0.x));
                    o0.y = fmaxf(0.f, sc * (a0.y + deg * bb0.y));
                    o0.z = fmaxf(0.f, sc * (a0.z + deg * bb0.z));
                    o0.w = fmaxf(0.f, sc * (a0.w + deg * bb0.w));
                    o1.x = fmaxf(0.f, sc * (a1.x + deg * bb1.x));
                    o1.y = fmaxf(0.f, sc * (a1.y + deg * bb1.y));
                    o1.z = fmaxf(0.f, sc * (a1.z + deg * bb1.z));
                    o1.w = fmaxf(0.f, sc * (a1.w + deg * bb1.w));
                    uint4 pk;
                    __half2 h0 = __floats2half2_rn(o0.x, o0.y);
                    __half2 h1 = __floats2half2_rn(o0.z, o0.w);
                    __half2 h2 = __floats2half2_rn(o1.x, o1.y);
                    __half2 h3 = __floats2half2_rn(o1.z, o1.w);
                    pk.x = *reinterpret_cast<unsigned*>(&h0);
                    pk.y = *reinterpret_cast<unsigned*>(&h1);
                    pk.z = *reinterpret_cast<unsigned*>(&h2);
                    pk.w = *reinterpret_cast<unsigned*>(&h3);
                    *reinterpret_cast<uint4*>(&As[m * AS_STRIDE + li * 8]) = pk;
                }
            } else if (eo == 0) {
                *reinterpret_cast<uint4*>(&As[m * AS_STRIDE + li * 8]) =
                    make_uint4(0, 0, 0, 0);
            }
        }
        __syncthreads();

        // ---- HMMA GEMM: 64x64 tile; 16 warps, 1 m-tile x 2 n-tiles each ----
        {
            const int mt = warp >> 2;
            const int nt0 = (warp & 3) * 2;
            const int m0 = mt * 16;

            float acc[2][4];
#pragma unroll
            for (int i = 0; i < 2; i++)
#pragma unroll
                for (int j = 0; j < 4; j++) acc[i][j] = 0.f;

#pragma unroll
            for (int kk = 0; kk < 8; kk++) {
                uint32_t a0, a1, a2, a3;
                uint32_t aaddr = smem_u32(
                    &As[(m0 + (lane & 15)) * AS_STRIDE + kk * 16 + ((lane >> 4) << 3)]);
                asm volatile("ldmatrix.sync.aligned.m8n8.x4.shared.b16 {%0,%1,%2,%3}, [%4];"
                             : "=r"(a0), "=r"(a1), "=r"(a2), "=r"(a3) : "r"(aaddr));
#pragma unroll
                for (int j = 0; j < 2; j++) {
                    uint32_t b0, b1;
                    uint32_t baddr = smem_u32(
                        &Ws[(kk * 16 + (lane & 15)) * WS_STRIDE + (nt0 + j) * 8]);
                    asm volatile("ldmatrix.sync.aligned.m8n8.x2.trans.shared.b16 {%0,%1}, [%2];"
                                 : "=r"(b0), "=r"(b1) : "r"(baddr));
                    asm volatile(
                        "mma.sync.aligned.m16n8k16.row.col.f32.f16.f16.f32 "
                        "{%0,%1,%2,%3}, {%4,%5,%6,%7}, {%8,%9}, {%0,%1,%2,%3};"
                        : "+f"(acc[j][0]), "+f"(acc[j][1]),
                          "+f"(acc[j][2]), "+f"(acc[j][3])
                        : "r"(a0), "r"(a1), "r"(a2), "r"(a3), "r"(b0), "r"(b1));
                }
            }

            const int g = lane >> 2, tg = lane & 3;
            const int r0 = row0 + m0 + g;
            const int r1 = r0 + 8;
#pragma unroll
            for (int j = 0; j < 2; j++) {
                int col = (nt0 + j) * 8 + 2 * tg;
                float bb0 = __ldg(b2 + col), bb1 = __ldg(b2 + col + 1);
                if (r0 < N)
                    *reinterpret_cast<__half2*>(&y2[(size_t)r0 * OUTC + col]) =
                        __floats2half2_rn(acc[j][0] + bb0, acc[j][1] + bb1);
                if (r1 < N)
                    *reinterpret_cast<__half2*>(&y2[(size_t)r1 * OUTC + col]) =
                        __floats2half2_rn(acc[j][2] + bb0, acc[j][3] + bb1);
            }
        }
        __syncthreads();   // As reused next tile
    }
}

// ---------------------------------------------------------------------------
// Wide-gather pull-agg layer 2 + log_softmax (R14 version: 16 lanes x uint2
// per 128B row, 16 edges/burst, unclamped pipelined prefetch, fp16 tree).
// Re-zeros g_cnt for next replay.
// ---------------------------------------------------------------------------
__global__ void __launch_bounds__(256)
pull_agg64_lsm_kernel(const __half* __restrict__ Yh,
                      const float* __restrict__ curv,
                      float* __restrict__ out, int N) {
    int gid = blockIdx.x * blockDim.x + threadIdx.x;
    if (gid < N) g_cnt[gid] = 0;   // prepare count buffer for next replay

    int warp = gid >> 5;
    int lane = threadIdx.x & 31;
    if (warp >= N) return;
    const uint2* Yv = reinterpret_cast<const uint2*>(Yh);  // row = 16 uint2
    const int eo = lane >> 4;
    const int li = lane & 15;

    float4 acc = make_float4(0.f, 0.f, 0.f, 0.f);
    if (eo == 0)
        acc = cvt_h4(__ldg(Yv + (size_t)warp * 16 + li));  // self loop
    int st = g_off[warp], en = g_off[warp + 1];
    int i = st;
    int s[8];
#pragma unroll
    for (int j = 0; j < 8; j++)
        s[j] = __ldg(g_csr + i + 2 * j + eo);       // unclamped
    for (; i + 16 <= en; ) {
        uint2 u[8];
#pragma unroll
        for (int j = 0; j < 8; j++)
            u[j] = __ldg(Yv + (size_t)s[j] * 16 + li);
        i += 16;
#pragma unroll
        for (int j = 0; j < 8; j++)
            s[j] = __ldg(g_csr + i + 2 * j + eo);   // unclamped prefetch
        tree8(u, acc);
    }
    if (i < en) {
        uint2 u[8];
#pragma unroll
        for (int j = 0; j < 8; j++) {
            u[j] = __ldg(Yv + (size_t)s[j] * 16 + li);
            if (i + 2 * j + eo >= en) u[j] = make_uint2(0, 0);
        }
        tree8(u, acc);
    }
    // merge half-warps
    acc.x += __shfl_xor_sync(~0u, acc.x, 16);
    acc.y += __shfl_xor_sync(~0u, acc.y, 16);
    acc.z += __shfl_xor_sync(~0u, acc.z, 16);
    acc.w += __shfl_xor_sync(~0u, acc.w, 16);

    float sc = -fabsf(__ldg(curv));
    float a0 = sc * acc.x, a1 = sc * acc.y, a2 = sc * acc.z, a3 = sc * acc.w;
    float m = fmaxf(fmaxf(a0, a1), fmaxf(a2, a3));
#pragma unroll
    for (int o = 8; o; o >>= 1) m = fmaxf(m, __shfl_xor_sync(~0u, m, o));
    float sum = expf(a0 - m) + expf(a1 - m) + expf(a2 - m) + expf(a3 - m);
#pragma unroll
    for (int o = 8; o; o >>= 1) sum += __shfl_xor_sync(~0u, sum, o);
    float lse = m + logf(sum);
    if (eo == 0) {
        float4 o4 = make_float4(a0 - lse, a1 - lse, a2 - lse, a3 - lse);
        *reinterpret_cast<float4*>(&out[(size_t)warp * OUTC + li * 4]) = o4;
    }
}

// ---------------------------------------------------------------------------
// Launch. Submission order: count_scan #1, scatter #2, gemm1 #3,
// agg_gemm #4 (ncu capture slot), lsm #5.
// ---------------------------------------------------------------------------
extern "C" void kernel_launch(void* const* d_in, const int* in_sizes, int n_in,
                              void* d_out, int out_size) {
    const float* x   = (const float*)d_in[0];
    const int*   ei  = (const int*)d_in[1];
    const float* W1  = (const float*)d_in[2];
    const float* b1  = (const float*)d_in[3];
    const float* cv1 = (const float*)d_in[6];
    const float* W2  = (const float*)d_in[7];
    const float* b2  = (const float*)d_in[8];
    const float* cv2 = (const float*)d_in[11];
    float* out = (float*)d_out;

    int N = in_sizes[0] / HID;
    int E = in_sizes[1] / 2;
    if (N > MAXN) N = MAXN;
    if (E > MAXE) E = MAXE;
    const int* src = ei;
    const int* dst = ei + E;
    int E2 = E / 2;

    void *y1p, *y2p;
    cudaGetSymbolAddress(&y1p, g_y1h);
    cudaGetSymbolAddress(&y2p, g_y2h);

    cudaFuncSetAttribute(agg_gemm_kernel,
                         cudaFuncAttributeMaxDynamicSharedMemorySize, FUSE_SMEM);
    cudaFuncSetAttribute(gemm1_kernel,
                         cudaFuncAttributeMaxDynamicSharedMemorySize, G1_SMEM);

    // Fork: CSR build on side stream (overlaps gemm1)
    cudaEventRecord(g_evA, 0);
    cudaStreamWaitEvent(g_s1, g_evA, 0);
    count_scan_kernel<<<(E2 + 1023) / 1024, 1024, 0, g_s1>>>(dst, E2, N); // #1
    scatter_kernel<<<(E2 + 255) / 256, 256, 0, g_s1>>>(src, dst, E2);     // #2
    cudaEventRecord(g_evB, g_s1);

    // Main stream: y1 = half(x @ W1) on tensor cores
    gemm1_kernel<<<(N + 127) / 128, 256, G1_SMEM>>>(x, W1, (__half*)y1p, N); // #3

    // Join, then persistent fused agg1+epi+HMMA gemm2 (capture slot #4)
    cudaStreamWaitEvent(0, g_evB, 0);
    int pblocks = 296;                       // 148 SMs x 2 blocks/SM
    int ntiles = (N + 63) / 64;
    if (pblocks > ntiles) pblocks = ntiles;
    agg_gemm_kernel<<<pblocks, 512, FUSE_SMEM>>>(
        (const __half*)y1p, W2, b1, b2, cv1, (__half*)y2p, N);            // #4

    // agg2 + log_softmax fused (+ g_cnt re-zero for next replay)
    pull_agg64_lsm_kernel<<<(N * 32 + 255) / 256, 256>>>(
        (const __half*)y2p, cv2, out, N);                                 // #5
}